// round 16
// baseline (speedup 1.0000x reference)
#include <cuda_runtime.h>
#include <cuda_fp16.h>
#include <cstdint>

// Problem constants
#define BB 2
#define LL 2048
#define DD 1024
#define HH 16
#define DKH 64
#define MTOT (BB*LL)   // 4096

// ---------------------------------------------------------------------------
// Scratch (no cudaMalloc allowed) — fp16 operands
// ---------------------------------------------------------------------------
__device__ __half g_xh[MTOT*DD];
__device__ __half g_wh[4*DD*DD];
__device__ __half g_q[BB*HH*LL*DKH];
__device__ __half g_k[BB*HH*LL*DKH];
__device__ __half g_v[BB*HH*LL*DKH];
__device__ __half g_oh[MTOT*DD];

__device__ __forceinline__ uint32_t smem_to_u32(const void* p) {
    uint32_t a;
    asm("{ .reg .u64 t; cvta.to.shared.u64 t, %1; cvt.u32.u64 %0, t; }" : "=r"(a) : "l"(p));
    return a;
}
#define SMEM_SWIZZLE_128B(o) ((o) ^ (((o) >> 3) & 0x70))

#define CP_ASYNC16(dst_u32, gptr) \
    asm volatile("cp.async.cg.shared.global [%0], [%1], 16;" \
                 :: "r"(dst_u32), "l"(gptr) : "memory")
#define CP_COMMIT() asm volatile("cp.async.commit_group;" ::: "memory")
#define CP_WAIT0()  asm volatile("cp.async.wait_group 0;" ::: "memory")
#define CP_WAIT1()  asm volatile("cp.async.wait_group 1;" ::: "memory")

__device__ __forceinline__ void ldmx4(uint32_t* r, uint32_t addr) {
    asm volatile("ldmatrix.sync.aligned.m8n8.x4.shared.b16 {%0,%1,%2,%3}, [%4];"
                 : "=r"(r[0]), "=r"(r[1]), "=r"(r[2]), "=r"(r[3]) : "r"(addr));
}
__device__ __forceinline__ void ldmx4t(uint32_t* r, uint32_t addr) {
    asm volatile("ldmatrix.sync.aligned.m8n8.x4.trans.shared.b16 {%0,%1,%2,%3}, [%4];"
                 : "=r"(r[0]), "=r"(r[1]), "=r"(r[2]), "=r"(r[3]) : "r"(addr));
}
__device__ __forceinline__ void mma_f16(float* c, const uint32_t* a, const uint32_t* b) {
    asm volatile("mma.sync.aligned.m16n8k16.row.col.f32.f16.f16.f32 "
                 "{%0,%1,%2,%3}, {%4,%5,%6,%7}, {%8,%9}, {%0,%1,%2,%3};"
                 : "+f"(c[0]), "+f"(c[1]), "+f"(c[2]), "+f"(c[3])
                 : "r"(a[0]), "r"(a[1]), "r"(a[2]), "r"(a[3]), "r"(b[0]), "r"(b[1]));
}
__device__ __forceinline__ uint32_t pack_f16(float x, float y) {
    __half2 h = __floats2half2_rn(x, y);
    uint32_t u; __builtin_memcpy(&u, &h, 4);
    return u;
}

// ---------------------------------------------------------------------------
// Fused fp32 -> fp16 convert for x + 4 weights (one launch)
// ---------------------------------------------------------------------------
__global__ void convert_all(const float* __restrict__ x,
                            const float* __restrict__ wq, const float* __restrict__ wk,
                            const float* __restrict__ wv, const float* __restrict__ wo,
                            __half* __restrict__ xh, __half* __restrict__ wh) {
    const int bid = blockIdx.x;
    const float* src;
    __half* dst;
    int i;
    if (bid < 4096) {
        src = x; dst = xh;
        i = bid * 256 + threadIdx.x;
    } else {
        const int wsel = (bid - 4096) >> 10;
        const int lb   = (bid - 4096) & 1023;
        src = (wsel == 0) ? wq : (wsel == 1) ? wk : (wsel == 2) ? wv : wo;
        dst = wh + (size_t)wsel * DD * DD;
        i = lb * 256 + threadIdx.x;
    }
    float4 v = ((const float4*)src)[i];
    ((__half2*)dst)[i*2+0] = __floats2half2_rn(v.x, v.y);
    ((__half2*)dst)[i*2+1] = __floats2half2_rn(v.z, v.w);
}

// ---------------------------------------------------------------------------
// QKV GEMM: CTA 64x128, 4 warps (2M x 2N, warp 32x64), BK=128 per chunk
// (8 chunks), each chunk stored as TWO 128B-row half-subtiles (kh=0: k[0,64),
// kh=1: k[64,128)) so swizzle/ldmatrix addressing is unchanged.
// Stage 48KB (A0@0 8K, A1@8K, B0@16K 16K, B1@32K), 2 stages, 2 CTA/SM.
// Fused QKV: blockIdx.y 0..23, wsel = y>>3, nBase = (y&7)*128.
// ---------------------------------------------------------------------------
#define QKV_SMEM (2*49152)
#define QKV_NCHUNK 8

__global__ void __launch_bounds__(128, 2) qkv_gemm(
        const __half* __restrict__ A, const __half* __restrict__ WB,
        const float* __restrict__ bias0, const float* __restrict__ bias1,
        const float* __restrict__ bias2,
        __half* __restrict__ c0, __half* __restrict__ c1, __half* __restrict__ c2) {
    extern __shared__ char sm[];
    const uint32_t sbase = smem_to_u32(sm);

    const int tid  = threadIdx.x;
    const int wid  = tid >> 5, lane = tid & 31;
    const int wm   = wid & 1, wn = wid >> 1;          // 2 x 2 warps, 32x64 each
    const int mBase = blockIdx.x * 64;

    const int wsel  = blockIdx.y >> 3;
    const int nBase = (blockIdx.y & 7) * 128;
    const __half* B = WB + (size_t)wsel * DD * DD;
    const float* bias = (wsel == 0) ? bias0 : (wsel == 1) ? bias1 : bias2;

    float acc[2][8][4] = {};

    const int aRow = (lane & 15);
    const int aKb  = (lane >> 4) * 16;
    const int bRow = ((lane >> 4) & 1) * 8 + (lane & 7);
    const int bKb  = ((lane >> 3) & 1) * 16;

    // loader: (64 A-rows + 128 B-rows) x 16 segs(16B) = 3072 / 128 thr = 24
    auto issue_chunk = [&](int k0, int st) {
        #pragma unroll
        for (int it = 0; it < 24; it++) {
            const int u = it * 128 + tid;
            const uint32_t stb = sbase + st * 49152;
            if (u < 1024) {
                const int row = u >> 4, seg = u & 15;
                const int kh = seg >> 3, s8 = seg & 7;
                CP_ASYNC16(stb + kh * 8192 + SMEM_SWIZZLE_128B(row * 128 + s8 * 16),
                           A + (size_t)(mBase + row) * DD + k0 + seg * 8);
            } else {
                const int idx = u - 1024;
                const int row = idx >> 4, seg = idx & 15;
                const int kh = seg >> 3, s8 = seg & 7;
                CP_ASYNC16(stb + 16384 + kh * 16384 + SMEM_SWIZZLE_128B(row * 128 + s8 * 16),
                           B + (size_t)(nBase + row) * DD + k0 + seg * 8);
            }
        }
    };

    issue_chunk(0, 0);
    CP_COMMIT();

    for (int c = 0; c < QKV_NCHUNK; c++) {
        CP_WAIT0();
        __syncthreads();
        if (c + 1 < QKV_NCHUNK) {
            issue_chunk((c + 1) * 128, (c + 1) & 1);
            CP_COMMIT();
        }
        const uint32_t sb0 = sbase + (c & 1) * 49152;

        #pragma unroll
        for (int kh = 0; kh < 2; kh++) {
            const uint32_t aB = sb0 + kh * 8192;
            const uint32_t bB = sb0 + 16384 + kh * 16384;
            #pragma unroll
            for (int ks = 0; ks < 4; ks++) {
                uint32_t bF[8][2];
                #pragma unroll
                for (int p = 0; p < 4; p++) {
                    const uint32_t bb = (wn * 64 + p * 16 + bRow) * 128 + ks * 32 + bKb;
                    uint32_t r[4];
                    ldmx4(r, bB + SMEM_SWIZZLE_128B(bb));
                    bF[p*2+0][0] = r[0]; bF[p*2+0][1] = r[1];
                    bF[p*2+1][0] = r[2]; bF[p*2+1][1] = r[3];
                }
                #pragma unroll
                for (int mf = 0; mf < 2; mf++) {
                    const uint32_t ab = (wm * 32 + mf * 16 + aRow) * 128 + ks * 32 + aKb;
                    uint32_t aF[4];
                    ldmx4(aF, aB + SMEM_SWIZZLE_128B(ab));
                    #pragma unroll
                    for (int nf = 0; nf < 8; nf++)
                        mma_f16(acc[mf][nf], aF, bF[nf]);
                }
            }
        }
    }

    __half* Ch = (wsel == 0) ? c0 : (wsel == 1) ? c1 : c2;

    const int rEp = lane >> 2, cEp = (lane & 3) * 2;
    #pragma unroll
    for (int mf = 0; mf < 2; mf++) {
        #pragma unroll
        for (int nf = 0; nf < 8; nf++) {
            const int m0 = mBase + wm * 32 + mf * 16 + rEp;
            const int n  = nBase + wn * 64 + nf * 8 + cEp;
            const float b0 = bias[n], b1 = bias[n + 1];
            float2 v0 = make_float2(acc[mf][nf][0] + b0, acc[mf][nf][1] + b1);
            float2 v1 = make_float2(acc[mf][nf][2] + b0, acc[mf][nf][3] + b1);
            const int h = n >> 6, dk = n & 63;
            const int b_ = m0 / LL, l0 = m0 % LL, l1 = l0 + 8;
            const size_t i0 = (((size_t)b_ * HH + h) * LL + l0) * DKH + dk;
            const size_t i1 = (((size_t)b_ * HH + h) * LL + l1) * DKH + dk;
            *(__half2*)(Ch + i0) = __floats2half2_rn(v0.x, v0.y);
            *(__half2*)(Ch + i1) = __floats2half2_rn(v1.x, v1.y);
        }
    }
}

// ---------------------------------------------------------------------------
// Output projection GEMM (R11/R12 config, unchanged): CTA 128x256,
// warp tile 64x64, grid (32, 4) = 128 CTAs = one balanced wave.
// ---------------------------------------------------------------------------
#define GEMM256_SMEM (3*49152)
#define NCHUNK 16

__global__ void __launch_bounds__(256, 1) out_gemm(
        const __half* __restrict__ A, const __half* __restrict__ B,
        const float* __restrict__ bias, float* __restrict__ C) {
    extern __shared__ char sm[];
    const uint32_t sbase = smem_to_u32(sm);

    const int tid  = threadIdx.x;
    const int wid  = tid >> 5, lane = tid & 31;
    const int wm   = wid & 1, wn = wid >> 1;
    const int mBase = blockIdx.x * 128;
    const int nBase = blockIdx.y * 256;

    float acc[4][8][4] = {};

    const int aRow = (lane & 15);
    const int aKb  = (lane >> 4) * 16;
    const int bRow = ((lane >> 4) & 1) * 8 + (lane & 7);
    const int bKb  = ((lane >> 3) & 1) * 16;

    auto issue_chunk = [&](int k0, int st) {
        #pragma unroll
        for (int it = 0; it < 12; it++) {
            const int u = it * 256 + tid;
            const uint32_t stb = sbase + st * 49152;
            if (u < 1024) {
                const int row = u >> 3, seg = u & 7;
                CP_ASYNC16(stb + SMEM_SWIZZLE_128B(row * 128 + seg * 16),
                           A + (size_t)(mBase + row) * DD + k0 + seg * 8);
            } else {
                const int idx = u - 1024;
                const int row = idx >> 3, seg = idx & 7;
                CP_ASYNC16(stb + 16384 + SMEM_SWIZZLE_128B(row * 128 + seg * 16),
                           B + (size_t)(nBase + row) * DD + k0 + seg * 8);
            }
        }
    };

    issue_chunk(0, 0);
    CP_COMMIT();
    issue_chunk(64, 1);
    CP_COMMIT();

    int stC = 0, stI = 2;
    for (int c = 0; c < NCHUNK; c++) {
        if (c == NCHUNK - 1) CP_WAIT0(); else CP_WAIT1();
        __syncthreads();
        if (c + 2 < NCHUNK) {
            issue_chunk((c + 2) * 64, stI);
            CP_COMMIT();
            if (++stI == 3) stI = 0;
        }
        const uint32_t sb0 = sbase + stC * 49152;
        if (++stC == 3) stC = 0;

        #pragma unroll
        for (int ks = 0; ks < 4; ks++) {
            uint32_t bF[8][2];
            #pragma unroll
            for (int p = 0; p < 4; p++) {
                const uint32_t bb = (wn * 64 + p * 16 + bRow) * 128 + ks * 32 + bKb;
                uint32_t r[4];
                ldmx4(r, sb0 + 16384 + SMEM_SWIZZLE_128B(bb));
                bF[p*2+0][0] = r[0]; bF[p*2+0][1] = r[1];
                bF[p*2+1][0] = r[2]; bF[p*2+1][1] = r[3];
            }
            #pragma unroll
            for (int mf = 0; mf < 4; mf++) {
                const uint32_t ab = (wm * 64 + mf * 16 + aRow) * 128 + ks * 32 + aKb;
                uint32_t aF[4];
                ldmx4(aF, sb0 + SMEM_SWIZZLE_128B(ab));
                #pragma unroll
                for (int nf = 0; nf < 8; nf++)
                    mma_f16(acc[mf][nf], aF, bF[nf]);
            }
        }
    }

    const int rEp = lane >> 2, cEp = (lane & 3) * 2;
    #pragma unroll
    for (int mf = 0; mf < 4; mf++) {
        #pragma unroll
        for (int nf = 0; nf < 8; nf++) {
            const int m0 = mBase + wm * 64 + mf * 16 + rEp;
            const int n  = nBase + wn * 64 + nf * 8 + cEp;
            const float b0 = bias[n], b1 = bias[n + 1];
            float2 v0 = make_float2(acc[mf][nf][0] + b0, acc[mf][nf][1] + b1);
            float2 v1 = make_float2(acc[mf][nf][2] + b0, acc[mf][nf][3] + b1);
            *(float2*)(C + (size_t)m0 * DD + n) = v0;
            *(float2*)(C + (size_t)(m0 + 8) * DD + n) = v1;
        }
    }
}

// ---------------------------------------------------------------------------
// fp16 tensor-core causal flash attention (unchanged R13 winner):
// BQ=64, BKV=64, 4 warps, 4 CTA/SM, longest-first CTA order.
// smem: Q@0 (8KB); stage s at 8K+s*16K: K@+0, V@+8K. Total 40KB.
// ---------------------------------------------------------------------------
#define ATT_SMEM (8192 + 2*16384)
#define SCL2 0.18033688011112042f   // (1/8) * log2(e)

__global__ void __launch_bounds__(128, 4) attn_mma(
        const __half* __restrict__ Q, const __half* __restrict__ K,
        const __half* __restrict__ V, __half* __restrict__ O) {
    extern __shared__ char sm[];
    const uint32_t sb = smem_to_u32(sm);

    const int tid = threadIdx.x, wid = tid >> 5, lane = tid & 31;
    const int qb = gridDim.x - 1 - blockIdx.x;   // longest-first
    const int bh = blockIdx.y;

    auto issue_kv = [&](int kb, int st) {
        #pragma unroll
        for (int it = 0; it < 8; it++) {
            const int u = it * 128 + tid;
            const int arr = u >> 9, idx = u & 511;
            const int row = idx >> 3, seg = idx & 7;
            const __half* src = arr ? V : K;
            const uint32_t d = sb + 8192 + st * 16384 + arr * 8192
                             + SMEM_SWIZZLE_128B(row * 128 + seg * 16);
            CP_ASYNC16(d, src + ((size_t)bh * LL + kb * 64 + row) * DKH + seg * 8);
        }
    };

    #pragma unroll
    for (int it = 0; it < 4; it++) {
        const int u = it * 128 + tid;
        const int row = u >> 3, seg = u & 7;
        const uint32_t d = sb + SMEM_SWIZZLE_128B(row * 128 + seg * 16);
        CP_ASYNC16(d, Q + ((size_t)bh * LL + qb * 64 + row) * DKH + seg * 8);
    }
    issue_kv(0, 0);
    CP_COMMIT();

    float s[8][4];
    float o[8][4] = {};
    float m0 = -1e30f, m1 = -1e30f, l0 = 0.0f, l1 = 0.0f;

    const int r0 = lane >> 2;
    const int ig0 = qb * 64 + wid * 16 + r0, ig1 = ig0 + 8;
    const int aRow = lane & 15;
    const int aKb  = (lane >> 4) * 16;
    const int bRow = ((lane >> 4) & 1) * 8 + (lane & 7);
    const int bKb  = ((lane >> 3) & 1) * 16;
    const int vseg = lane >> 3;
    const int vr   = (vseg & 1) * 8 + (lane & 7);
    const int vcB  = (vseg >> 1) * 16;

    const int kbmax = qb;
    for (int kb = 0; kb <= kbmax; kb++) {
        CP_WAIT0();
        __syncthreads();
        if (kb < kbmax) {
            issue_kv(kb + 1, (kb + 1) & 1);
            CP_COMMIT();
        }

        const uint32_t kvb = sb + 8192 + (kb & 1) * 16384;

        // ---- S = Q K^T, fragment-pipelined ----
        #pragma unroll
        for (int nf = 0; nf < 8; nf++)
            s[nf][0] = s[nf][1] = s[nf][2] = s[nf][3] = 0.0f;
        {
            uint32_t ah[2][4], kF[2][4];
            auto loadQf = [&](int ks, int buf) {
                const uint32_t ao = SMEM_SWIZZLE_128B((wid * 16 + aRow) * 128 + ks * 32 + aKb);
                ldmx4(ah[buf], sb + ao);
            };
            auto loadKf = [&](int ks, int p, int buf) {
                const uint32_t bo = SMEM_SWIZZLE_128B((p * 16 + bRow) * 128 + ks * 32 + bKb);
                ldmx4(kF[buf], kvb + bo);
            };
            loadQf(0, 0);
            loadKf(0, 0, 0);
            #pragma unroll
            for (int ks = 0; ks < 4; ks++) {
                const int cq = ks & 1;
                #pragma unroll
                for (int p = 0; p < 4; p++) {
                    const int ck = (ks * 4 + p) & 1;
                    if (p < 3)       loadKf(ks, p + 1, ck ^ 1);
                    else if (ks < 3) { loadQf(ks + 1, cq ^ 1); loadKf(ks + 1, 0, ck ^ 1); }
                    mma_f16(s[2*p],   ah[cq], kF[ck]);
                    mma_f16(s[2*p+1], ah[cq], kF[ck] + 2);
                }
            }
        }

        // ---- online softmax in exp2 domain (quad shuffles) ----
        const bool needMask = (kb == qb);
        float mx0 = -1e30f, mx1 = -1e30f;
        #pragma unroll
        for (int nf = 0; nf < 8; nf++) {
            #pragma unroll
            for (int c = 0; c < 4; c++) {
                float v = s[nf][c] * SCL2;
                if (needMask) {
                    const int jg = kb * 64 + nf * 8 + 2 * (lane & 3) + (c & 1);
                    if (jg > ((c < 2) ? ig0 : ig1)) v = -1e30f;
                }
                s[nf][c] = v;
            }
            mx0 = fmaxf(mx0, fmaxf(s[nf][0], s[nf][1]));
            mx1 = fmaxf(mx1, fmaxf(s[nf][2], s[nf][3]));
        }
        mx0 = fmaxf(mx0, __shfl_xor_sync(~0u, mx0, 1));
        mx0 = fmaxf(mx0, __shfl_xor_sync(~0u, mx0, 2));
        mx1 = fmaxf(mx1, __shfl_xor_sync(~0u, mx1, 1));
        mx1 = fmaxf(mx1, __shfl_xor_sync(~0u, mx1, 2));
        const float mn0 = fmaxf(m0, mx0), mn1 = fmaxf(m1, mx1);
        const float al0 = exp2f(m0 - mn0), al1 = exp2f(m1 - mn1);
        m0 = mn0; m1 = mn1;
        float rs0 = 0.0f, rs1 = 0.0f;
        #pragma unroll
        for (int nf = 0; nf < 8; nf++) {
            s[nf][0] = exp2f(s[nf][0] - mn0);
            s[nf][1] = exp2f(s[nf][1] - mn0);
            s[nf][2] = exp2f(s[nf][2] - mn1);
            s[nf][3] = exp2f(s[nf][3] - mn1);
            rs0 += s[nf][0] + s[nf][1];
            rs1 += s[nf][2] + s[nf][3];
        }
        rs0 += __shfl_xor_sync(~0u, rs0, 1);
        rs0 += __shfl_xor_sync(~0u, rs0, 2);
        rs1 += __shfl_xor_sync(~0u, rs1, 1);
        rs1 += __shfl_xor_sync(~0u, rs1, 2);
        l0 = l0 * al0 + rs0;
        l1 = l1 * al1 + rs1;
        #pragma unroll
        for (int nf = 0; nf < 8; nf++) {
            o[nf][0] *= al0; o[nf][1] *= al0;
            o[nf][2] *= al1; o[nf][3] *= al1;
        }

        // ---- O += P V, V-fragment pipelined ----
        {
            uint32_t vF[2][4];
            auto loadVf = [&](int ks, int q, int buf) {
                const uint32_t vo = SMEM_SWIZZLE_128B((ks * 16 + vr) * 128 + q * 32 + vcB);
                ldmx4t(vF[buf], kvb + 8192 + vo);
            };
            loadVf(0, 0, 0);
            #pragma unroll
            for (int ks = 0; ks < 4; ks++) {
                uint32_t aph[4];
                aph[0] = pack_f16(s[2*ks][0],   s[2*ks][1]);
                aph[1] = pack_f16(s[2*ks][2],   s[2*ks][3]);
                aph[2] = pack_f16(s[2*ks+1][0], s[2*ks+1][1]);
                aph[3] = pack_f16(s[2*ks+1][2], s[2*ks+1][3]);
                #pragma unroll
                for (int q = 0; q < 4; q++) {
                    const int cv = (ks * 4 + q) & 1;
                    if (q < 3)       loadVf(ks, q + 1, cv ^ 1);
                    else if (ks < 3) loadVf(ks + 1, 0, cv ^ 1);
                    mma_f16(o[2*q],   aph, vF[cv]);
                    mma_f16(o[2*q+1], aph, vF[cv] + 2);
                }
            }
        }
    }

    // Epilogue: normalize, convert fp16, scatter to (B, L, D)
    const int b = bh >> 4, h = bh & 15;
    const float inv0 = 1.0f / l0, inv1 = 1.0f / l1;
    const int lg0 = qb * 64 + wid * 16 + r0, lg1 = lg0 + 8;
    #pragma unroll
    for (int nf = 0; nf < 8; nf++) {
        const int d = h * 64 + nf * 8 + 2 * (lane & 3);
        const size_t i0 = ((size_t)b * LL + lg0) * DD + d;
        const size_t i1 = ((size_t)b * LL + lg1) * DD + d;
        *(__half2*)(O + i0) = __floats2half2_rn(o[nf][0] * inv0, o[nf][1] * inv0);
        *(__half2*)(O + i1) = __floats2half2_rn(o[nf][2] * inv1, o[nf][3] * inv1);
    }
}

// ---------------------------------------------------------------------------
extern "C" void kernel_launch(void* const* d_in, const int* in_sizes, int n_in,
                              void* d_out, int out_size) {
    (void)in_sizes; (void)n_in; (void)out_size;
    const float* x  = (const float*)d_in[0];
    const float* wq = (const float*)d_in[1];
    const float* bq = (const float*)d_in[2];
    const float* wk = (const float*)d_in[3];
    const float* bk = (const float*)d_in[4];
    const float* wv = (const float*)d_in[5];
    const float* bv = (const float*)d_in[6];
    const float* wo = (const float*)d_in[7];
    const float* bo = (const float*)d_in[8];

    __half *xh, *wh, *q, *k, *v, *oh;
    cudaGetSymbolAddress((void**)&xh, g_xh);
    cudaGetSymbolAddress((void**)&wh, g_wh);
    cudaGetSymbolAddress((void**)&q,  g_q);
    cudaGetSymbolAddress((void**)&k,  g_k);
    cudaGetSymbolAddress((void**)&v,  g_v);
    cudaGetSymbolAddress((void**)&oh, g_oh);

    convert_all<<<8192, 256>>>(x, wq, wk, wv, wo, xh, wh);

    cudaFuncSetAttribute(qkv_gemm, cudaFuncAttributeMaxDynamicSharedMemorySize, QKV_SMEM);
    cudaFuncSetAttribute(out_gemm, cudaFuncAttributeMaxDynamicSharedMemorySize, GEMM256_SMEM);
    cudaFuncSetAttribute(attn_mma, cudaFuncAttributeMaxDynamicSharedMemorySize, ATT_SMEM);

    // Fused Q,K,V projection: 64x128 tiles, BK=128, grid (64, 24), 2 CTA/SM
    qkv_gemm<<<dim3(MTOT / 64, 24), 128, QKV_SMEM>>>(
        xh, wh, bq, bk, bv, q, k, v);

    // Attention: BQ=64, grid (32, 32), 128 threads, 4 CTA/SM
    attn_mma<<<dim3(LL / 64, BB * HH), 128, ATT_SMEM>>>(q, k, v, oh);

    // Output projection: 128x256 tiles, grid (32, 4) = 128 CTAs, one wave
    out_gemm<<<dim3(MTOT / 128, 4), 256, GEMM256_SMEM>>>(
        oh, wh + 3*(size_t)DD*DD, bo, (float*)d_out);
}

// round 17
// speedup vs baseline: 1.0332x; 1.0332x over previous
#include <cuda_runtime.h>
#include <cuda_fp16.h>
#include <cstdint>

// Problem constants
#define BB 2
#define LL 2048
#define DD 1024
#define HH 16
#define DKH 64
#define MTOT (BB*LL)   // 4096

// ---------------------------------------------------------------------------
// Scratch (no cudaMalloc allowed) — fp16 operands
// ---------------------------------------------------------------------------
__device__ __half g_xh[MTOT*DD];
__device__ __half g_wh[4*DD*DD];
__device__ __half g_q[BB*HH*LL*DKH];
__device__ __half g_k[BB*HH*LL*DKH];
__device__ __half g_v[BB*HH*LL*DKH];
__device__ __half g_oh[MTOT*DD];

__device__ __forceinline__ uint32_t smem_to_u32(const void* p) {
    uint32_t a;
    asm("{ .reg .u64 t; cvta.to.shared.u64 t, %1; cvt.u32.u64 %0, t; }" : "=r"(a) : "l"(p));
    return a;
}
#define SMEM_SWIZZLE_128B(o) ((o) ^ (((o) >> 3) & 0x70))

#define CP_ASYNC16(dst_u32, gptr) \
    asm volatile("cp.async.cg.shared.global [%0], [%1], 16;" \
                 :: "r"(dst_u32), "l"(gptr) : "memory")
#define CP_COMMIT() asm volatile("cp.async.commit_group;" ::: "memory")
#define CP_WAIT0()  asm volatile("cp.async.wait_group 0;" ::: "memory")
#define CP_WAIT1()  asm volatile("cp.async.wait_group 1;" ::: "memory")

__device__ __forceinline__ void ldmx4(uint32_t* r, uint32_t addr) {
    asm volatile("ldmatrix.sync.aligned.m8n8.x4.shared.b16 {%0,%1,%2,%3}, [%4];"
                 : "=r"(r[0]), "=r"(r[1]), "=r"(r[2]), "=r"(r[3]) : "r"(addr));
}
__device__ __forceinline__ void ldmx4t(uint32_t* r, uint32_t addr) {
    asm volatile("ldmatrix.sync.aligned.m8n8.x4.trans.shared.b16 {%0,%1,%2,%3}, [%4];"
                 : "=r"(r[0]), "=r"(r[1]), "=r"(r[2]), "=r"(r[3]) : "r"(addr));
}
__device__ __forceinline__ void mma_f16(float* c, const uint32_t* a, const uint32_t* b) {
    asm volatile("mma.sync.aligned.m16n8k16.row.col.f32.f16.f16.f32 "
                 "{%0,%1,%2,%3}, {%4,%5,%6,%7}, {%8,%9}, {%0,%1,%2,%3};"
                 : "+f"(c[0]), "+f"(c[1]), "+f"(c[2]), "+f"(c[3])
                 : "r"(a[0]), "r"(a[1]), "r"(a[2]), "r"(a[3]), "r"(b[0]), "r"(b[1]));
}
__device__ __forceinline__ uint32_t pack_f16(float x, float y) {
    __half2 h = __floats2half2_rn(x, y);
    uint32_t u; __builtin_memcpy(&u, &h, 4);
    return u;
}

// ---------------------------------------------------------------------------
// Fused fp32 -> fp16 convert, 2 float4 per thread (MLP=2) for latency cover.
// grid 4096: blocks 0..2047 -> x (1M float4); 2048+ -> weights (256K each).
// ---------------------------------------------------------------------------
__global__ void convert_all(const float* __restrict__ x,
                            const float* __restrict__ wq, const float* __restrict__ wk,
                            const float* __restrict__ wv, const float* __restrict__ wo,
                            __half* __restrict__ xh, __half* __restrict__ wh) {
    const int bid = blockIdx.x;
    const float* src;
    __half* dst;
    int i;
    if (bid < 2048) {
        src = x; dst = xh;
        i = bid * 512 + threadIdx.x;
    } else {
        const int wsel = (bid - 2048) >> 9;
        const int lb   = (bid - 2048) & 511;
        src = (wsel == 0) ? wq : (wsel == 1) ? wk : (wsel == 2) ? wv : wo;
        dst = wh + (size_t)wsel * DD * DD;
        i = lb * 512 + threadIdx.x;
    }
    float4 v0 = ((const float4*)src)[i];
    float4 v1 = ((const float4*)src)[i + 256];
    ((__half2*)dst)[i*2+0] = __floats2half2_rn(v0.x, v0.y);
    ((__half2*)dst)[i*2+1] = __floats2half2_rn(v0.z, v0.w);
    ((__half2*)dst)[(i+256)*2+0] = __floats2half2_rn(v1.x, v1.y);
    ((__half2*)dst)[(i+256)*2+1] = __floats2half2_rn(v1.z, v1.w);
}

// ---------------------------------------------------------------------------
// QKV GEMM (R14 winner): CTA 64x128, 4 warps (2M x 2N, warp 32x64), BK=64,
// 3-stage cp.async (24KB/stage), 3 CTA/SM.
// Fused QKV: blockIdx.y 0..23, wsel = y>>3, nBase = (y&7)*128.
// ---------------------------------------------------------------------------
#define QKV_SMEM (3*24576)
#define NCHUNK 16

__global__ void __launch_bounds__(128, 3) qkv_gemm(
        const __half* __restrict__ A, const __half* __restrict__ WB,
        const float* __restrict__ bias0, const float* __restrict__ bias1,
        const float* __restrict__ bias2,
        __half* __restrict__ c0, __half* __restrict__ c1, __half* __restrict__ c2) {
    extern __shared__ char sm[];
    const uint32_t sbase = smem_to_u32(sm);

    const int tid  = threadIdx.x;
    const int wid  = tid >> 5, lane = tid & 31;
    const int wm   = wid & 1, wn = wid >> 1;          // 2 x 2 warps, 32x64 each
    const int mBase = blockIdx.x * 64;

    const int wsel  = blockIdx.y >> 3;
    const int nBase = (blockIdx.y & 7) * 128;
    const __half* B = WB + (size_t)wsel * DD * DD;
    const float* bias = (wsel == 0) ? bias0 : (wsel == 1) ? bias1 : bias2;

    float acc[2][8][4] = {};

    const int aRow = (lane & 15);
    const int aKb  = (lane >> 4) * 16;
    const int bRow = ((lane >> 4) & 1) * 8 + (lane & 7);
    const int bKb  = ((lane >> 3) & 1) * 16;

    auto issue_chunk = [&](int k0, int st) {
        #pragma unroll
        for (int it = 0; it < 12; it++) {
            const int u = it * 128 + tid;
            const uint32_t stb = sbase + st * 24576;
            if (u < 512) {
                const int row = u >> 3, seg = u & 7;
                CP_ASYNC16(stb + SMEM_SWIZZLE_128B(row * 128 + seg * 16),
                           A + (size_t)(mBase + row) * DD + k0 + seg * 8);
            } else {
                const int idx = u - 512;
                const int row = idx >> 3, seg = idx & 7;
                CP_ASYNC16(stb + 8192 + SMEM_SWIZZLE_128B(row * 128 + seg * 16),
                           B + (size_t)(nBase + row) * DD + k0 + seg * 8);
            }
        }
    };

    issue_chunk(0, 0);
    CP_COMMIT();
    issue_chunk(64, 1);
    CP_COMMIT();

    int stC = 0, stI = 2;
    for (int c = 0; c < NCHUNK; c++) {
        if (c == NCHUNK - 1) CP_WAIT0(); else CP_WAIT1();
        __syncthreads();
        if (c + 2 < NCHUNK) {
            issue_chunk((c + 2) * 64, stI);
            CP_COMMIT();
            if (++stI == 3) stI = 0;
        }
        const uint32_t sb0 = sbase + stC * 24576;
        if (++stC == 3) stC = 0;

        #pragma unroll
        for (int ks = 0; ks < 4; ks++) {
            uint32_t bF[8][2];
            #pragma unroll
            for (int p = 0; p < 4; p++) {
                const uint32_t bb = (wn * 64 + p * 16 + bRow) * 128 + ks * 32 + bKb;
                uint32_t r[4];
                ldmx4(r, sb0 + 8192 + SMEM_SWIZZLE_128B(bb));
                bF[p*2+0][0] = r[0]; bF[p*2+0][1] = r[1];
                bF[p*2+1][0] = r[2]; bF[p*2+1][1] = r[3];
            }
            #pragma unroll
            for (int mf = 0; mf < 2; mf++) {
                const uint32_t ab = (wm * 32 + mf * 16 + aRow) * 128 + ks * 32 + aKb;
                uint32_t aF[4];
                ldmx4(aF, sb0 + SMEM_SWIZZLE_128B(ab));
                #pragma unroll
                for (int nf = 0; nf < 8; nf++)
                    mma_f16(acc[mf][nf], aF, bF[nf]);
            }
        }
    }

    __half* Ch = (wsel == 0) ? c0 : (wsel == 1) ? c1 : c2;

    const int rEp = lane >> 2, cEp = (lane & 3) * 2;
    #pragma unroll
    for (int mf = 0; mf < 2; mf++) {
        #pragma unroll
        for (int nf = 0; nf < 8; nf++) {
            const int m0 = mBase + wm * 32 + mf * 16 + rEp;
            const int n  = nBase + wn * 64 + nf * 8 + cEp;
            const float b0 = bias[n], b1 = bias[n + 1];
            float2 v0 = make_float2(acc[mf][nf][0] + b0, acc[mf][nf][1] + b1);
            float2 v1 = make_float2(acc[mf][nf][2] + b0, acc[mf][nf][3] + b1);
            const int h = n >> 6, dk = n & 63;
            const int b_ = m0 / LL, l0 = m0 % LL, l1 = l0 + 8;
            const size_t i0 = (((size_t)b_ * HH + h) * LL + l0) * DKH + dk;
            const size_t i1 = (((size_t)b_ * HH + h) * LL + l1) * DKH + dk;
            *(__half2*)(Ch + i0) = __floats2half2_rn(v0.x, v0.y);
            *(__half2*)(Ch + i1) = __floats2half2_rn(v1.x, v1.y);
        }
    }
}

// ---------------------------------------------------------------------------
// Output projection GEMM (R11/R12 config): CTA 128x256, warp tile 64x64,
// grid (32, 4) = 128 CTAs = one balanced wave. fp32 C row-major.
// ---------------------------------------------------------------------------
#define GEMM256_SMEM (3*49152)

__global__ void __launch_bounds__(256, 1) out_gemm(
        const __half* __restrict__ A, const __half* __restrict__ B,
        const float* __restrict__ bias, float* __restrict__ C) {
    extern __shared__ char sm[];
    const uint32_t sbase = smem_to_u32(sm);

    const int tid  = threadIdx.x;
    const int wid  = tid >> 5, lane = tid & 31;
    const int wm   = wid & 1, wn = wid >> 1;
    const int mBase = blockIdx.x * 128;
    const int nBase = blockIdx.y * 256;

    float acc[4][8][4] = {};

    const int aRow = (lane & 15);
    const int aKb  = (lane >> 4) * 16;
    const int bRow = ((lane >> 4) & 1) * 8 + (lane & 7);
    const int bKb  = ((lane >> 3) & 1) * 16;

    auto issue_chunk = [&](int k0, int st) {
        #pragma unroll
        for (int it = 0; it < 12; it++) {
            const int u = it * 256 + tid;
            const uint32_t stb = sbase + st * 49152;
            if (u < 1024) {
                const int row = u >> 3, seg = u & 7;
                CP_ASYNC16(stb + SMEM_SWIZZLE_128B(row * 128 + seg * 16),
                           A + (size_t)(mBase + row) * DD + k0 + seg * 8);
            } else {
                const int idx = u - 1024;
                const int row = idx >> 3, seg = idx & 7;
                CP_ASYNC16(stb + 16384 + SMEM_SWIZZLE_128B(row * 128 + seg * 16),
                           B + (size_t)(nBase + row) * DD + k0 + seg * 8);
            }
        }
    };

    issue_chunk(0, 0);
    CP_COMMIT();
    issue_chunk(64, 1);
    CP_COMMIT();

    int stC = 0, stI = 2;
    for (int c = 0; c < NCHUNK; c++) {
        if (c == NCHUNK - 1) CP_WAIT0(); else CP_WAIT1();
        __syncthreads();
        if (c + 2 < NCHUNK) {
            issue_chunk((c + 2) * 64, stI);
            CP_COMMIT();
            if (++stI == 3) stI = 0;
        }
        const uint32_t sb0 = sbase + stC * 49152;
        if (++stC == 3) stC = 0;

        #pragma unroll
        for (int ks = 0; ks < 4; ks++) {
            uint32_t bF[8][2];
            #pragma unroll
            for (int p = 0; p < 4; p++) {
                const uint32_t bb = (wn * 64 + p * 16 + bRow) * 128 + ks * 32 + bKb;
                uint32_t r[4];
                ldmx4(r, sb0 + 16384 + SMEM_SWIZZLE_128B(bb));
                bF[p*2+0][0] = r[0]; bF[p*2+0][1] = r[1];
                bF[p*2+1][0] = r[2]; bF[p*2+1][1] = r[3];
            }
            #pragma unroll
            for (int mf = 0; mf < 4; mf++) {
                const uint32_t ab = (wm * 64 + mf * 16 + aRow) * 128 + ks * 32 + aKb;
                uint32_t aF[4];
                ldmx4(aF, sb0 + SMEM_SWIZZLE_128B(ab));
                #pragma unroll
                for (int nf = 0; nf < 8; nf++)
                    mma_f16(acc[mf][nf], aF, bF[nf]);
            }
        }
    }

    const int rEp = lane >> 2, cEp = (lane & 3) * 2;
    #pragma unroll
    for (int mf = 0; mf < 4; mf++) {
        #pragma unroll
        for (int nf = 0; nf < 8; nf++) {
            const int m0 = mBase + wm * 64 + mf * 16 + rEp;
            const int n  = nBase + wn * 64 + nf * 8 + cEp;
            const float b0 = bias[n], b1 = bias[n + 1];
            float2 v0 = make_float2(acc[mf][nf][0] + b0, acc[mf][nf][1] + b1);
            float2 v1 = make_float2(acc[mf][nf][2] + b0, acc[mf][nf][3] + b1);
            *(float2*)(C + (size_t)m0 * DD + n) = v0;
            *(float2*)(C + (size_t)(m0 + 8) * DD + n) = v1;
        }
    }
}

// ---------------------------------------------------------------------------
// fp16 tensor-core causal flash attention (unchanged R13 winner):
// BQ=64, BKV=64, 4 warps, 4 CTA/SM, longest-first CTA order.
// smem: Q@0 (8KB); stage s at 8K+s*16K: K@+0, V@+8K. Total 40KB.
// ---------------------------------------------------------------------------
#define ATT_SMEM (8192 + 2*16384)
#define SCL2 0.18033688011112042f   // (1/8) * log2(e)

__global__ void __launch_bounds__(128, 4) attn_mma(
        const __half* __restrict__ Q, const __half* __restrict__ K,
        const __half* __restrict__ V, __half* __restrict__ O) {
    extern __shared__ char sm[];
    const uint32_t sb = smem_to_u32(sm);

    const int tid = threadIdx.x, wid = tid >> 5, lane = tid & 31;
    const int qb = gridDim.x - 1 - blockIdx.x;   // longest-first
    const int bh = blockIdx.y;

    auto issue_kv = [&](int kb, int st) {
        #pragma unroll
        for (int it = 0; it < 8; it++) {
            const int u = it * 128 + tid;
            const int arr = u >> 9, idx = u & 511;
            const int row = idx >> 3, seg = idx & 7;
            const __half* src = arr ? V : K;
            const uint32_t d = sb + 8192 + st * 16384 + arr * 8192
                             + SMEM_SWIZZLE_128B(row * 128 + seg * 16);
            CP_ASYNC16(d, src + ((size_t)bh * LL + kb * 64 + row) * DKH + seg * 8);
        }
    };

    #pragma unroll
    for (int it = 0; it < 4; it++) {
        const int u = it * 128 + tid;
        const int row = u >> 3, seg = u & 7;
        const uint32_t d = sb + SMEM_SWIZZLE_128B(row * 128 + seg * 16);
        CP_ASYNC16(d, Q + ((size_t)bh * LL + qb * 64 + row) * DKH + seg * 8);
    }
    issue_kv(0, 0);
    CP_COMMIT();

    float s[8][4];
    float o[8][4] = {};
    float m0 = -1e30f, m1 = -1e30f, l0 = 0.0f, l1 = 0.0f;

    const int r0 = lane >> 2;
    const int ig0 = qb * 64 + wid * 16 + r0, ig1 = ig0 + 8;
    const int aRow = lane & 15;
    const int aKb  = (lane >> 4) * 16;
    const int bRow = ((lane >> 4) & 1) * 8 + (lane & 7);
    const int bKb  = ((lane >> 3) & 1) * 16;
    const int vseg = lane >> 3;
    const int vr   = (vseg & 1) * 8 + (lane & 7);
    const int vcB  = (vseg >> 1) * 16;

    const int kbmax = qb;
    for (int kb = 0; kb <= kbmax; kb++) {
        CP_WAIT0();
        __syncthreads();
        if (kb < kbmax) {
            issue_kv(kb + 1, (kb + 1) & 1);
            CP_COMMIT();
        }

        const uint32_t kvb = sb + 8192 + (kb & 1) * 16384;

        // ---- S = Q K^T, fragment-pipelined ----
        #pragma unroll
        for (int nf = 0; nf < 8; nf++)
            s[nf][0] = s[nf][1] = s[nf][2] = s[nf][3] = 0.0f;
        {
            uint32_t ah[2][4], kF[2][4];
            auto loadQf = [&](int ks, int buf) {
                const uint32_t ao = SMEM_SWIZZLE_128B((wid * 16 + aRow) * 128 + ks * 32 + aKb);
                ldmx4(ah[buf], sb + ao);
            };
            auto loadKf = [&](int ks, int p, int buf) {
                const uint32_t bo = SMEM_SWIZZLE_128B((p * 16 + bRow) * 128 + ks * 32 + bKb);
                ldmx4(kF[buf], kvb + bo);
            };
            loadQf(0, 0);
            loadKf(0, 0, 0);
            #pragma unroll
            for (int ks = 0; ks < 4; ks++) {
                const int cq = ks & 1;
                #pragma unroll
                for (int p = 0; p < 4; p++) {
                    const int ck = (ks * 4 + p) & 1;
                    if (p < 3)       loadKf(ks, p + 1, ck ^ 1);
                    else if (ks < 3) { loadQf(ks + 1, cq ^ 1); loadKf(ks + 1, 0, ck ^ 1); }
                    mma_f16(s[2*p],   ah[cq], kF[ck]);
                    mma_f16(s[2*p+1], ah[cq], kF[ck] + 2);
                }
            }
        }

        // ---- online softmax in exp2 domain (quad shuffles) ----
        const bool needMask = (kb == qb);
        float mx0 = -1e30f, mx1 = -1e30f;
        #pragma unroll
        for (int nf = 0; nf < 8; nf++) {
            #pragma unroll
            for (int c = 0; c < 4; c++) {
                float v = s[nf][c] * SCL2;
                if (needMask) {
                    const int jg = kb * 64 + nf * 8 + 2 * (lane & 3) + (c & 1);
                    if (jg > ((c < 2) ? ig0 : ig1)) v = -1e30f;
                }
                s[nf][c] = v;
            }
            mx0 = fmaxf(mx0, fmaxf(s[nf][0], s[nf][1]));
            mx1 = fmaxf(mx1, fmaxf(s[nf][2], s[nf][3]));
        }
        mx0 = fmaxf(mx0, __shfl_xor_sync(~0u, mx0, 1));
        mx0 = fmaxf(mx0, __shfl_xor_sync(~0u, mx0, 2));
        mx1 = fmaxf(mx1, __shfl_xor_sync(~0u, mx1, 1));
        mx1 = fmaxf(mx1, __shfl_xor_sync(~0u, mx1, 2));
        const float mn0 = fmaxf(m0, mx0), mn1 = fmaxf(m1, mx1);
        const float al0 = exp2f(m0 - mn0), al1 = exp2f(m1 - mn1);
        m0 = mn0; m1 = mn1;
        float rs0 = 0.0f, rs1 = 0.0f;
        #pragma unroll
        for (int nf = 0; nf < 8; nf++) {
            s[nf][0] = exp2f(s[nf][0] - mn0);
            s[nf][1] = exp2f(s[nf][1] - mn0);
            s[nf][2] = exp2f(s[nf][2] - mn1);
            s[nf][3] = exp2f(s[nf][3] - mn1);
            rs0 += s[nf][0] + s[nf][1];
            rs1 += s[nf][2] + s[nf][3];
        }
        rs0 += __shfl_xor_sync(~0u, rs0, 1);
        rs0 += __shfl_xor_sync(~0u, rs0, 2);
        rs1 += __shfl_xor_sync(~0u, rs1, 1);
        rs1 += __shfl_xor_sync(~0u, rs1, 2);
        l0 = l0 * al0 + rs0;
        l1 = l1 * al1 + rs1;
        #pragma unroll
        for (int nf = 0; nf < 8; nf++) {
            o[nf][0] *= al0; o[nf][1] *= al0;
            o[nf][2] *= al1; o[nf][3] *= al1;
        }

        // ---- O += P V, V-fragment pipelined ----
        {
            uint32_t vF[2][4];
            auto loadVf = [&](int ks, int q, int buf) {
                const uint32_t vo = SMEM_SWIZZLE_128B((ks * 16 + vr) * 128 + q * 32 + vcB);
                ldmx4t(vF[buf], kvb + 8192 + vo);
            };
            loadVf(0, 0, 0);
            #pragma unroll
            for (int ks = 0; ks < 4; ks++) {
                uint32_t aph[4];
                aph[0] = pack_f16(s[2*ks][0],   s[2*ks][1]);
                aph[1] = pack_f16(s[2*ks][2],   s[2*ks][3]);
                aph[2] = pack_f16(s[2*ks+1][0], s[2*ks+1][1]);
                aph[3] = pack_f16(s[2*ks+1][2], s[2*ks+1][3]);
                #pragma unroll
                for (int q = 0; q < 4; q++) {
                    const int cv = (ks * 4 + q) & 1;
                    if (q < 3)       loadVf(ks, q + 1, cv ^ 1);
                    else if (ks < 3) loadVf(ks + 1, 0, cv ^ 1);
                    mma_f16(o[2*q],   aph, vF[cv]);
                    mma_f16(o[2*q+1], aph, vF[cv] + 2);
                }
            }
        }
    }

    // Epilogue: normalize, convert fp16, scatter to (B, L, D)
    const int b = bh >> 4, h = bh & 15;
    const float inv0 = 1.0f / l0, inv1 = 1.0f / l1;
    const int lg0 = qb * 64 + wid * 16 + r0, lg1 = lg0 + 8;
    #pragma unroll
    for (int nf = 0; nf < 8; nf++) {
        const int d = h * 64 + nf * 8 + 2 * (lane & 3);
        const size_t i0 = ((size_t)b * LL + lg0) * DD + d;
        const size_t i1 = ((size_t)b * LL + lg1) * DD + d;
        *(__half2*)(O + i0) = __floats2half2_rn(o[nf][0] * inv0, o[nf][1] * inv0);
        *(__half2*)(O + i1) = __floats2half2_rn(o[nf][2] * inv1, o[nf][3] * inv1);
    }
}

// ---------------------------------------------------------------------------
extern "C" void kernel_launch(void* const* d_in, const int* in_sizes, int n_in,
                              void* d_out, int out_size) {
    (void)in_sizes; (void)n_in; (void)out_size;
    const float* x  = (const float*)d_in[0];
    const float* wq = (const float*)d_in[1];
    const float* bq = (const float*)d_in[2];
    const float* wk = (const float*)d_in[3];
    const float* bk = (const float*)d_in[4];
    const float* wv = (const float*)d_in[5];
    const float* bv = (const float*)d_in[6];
    const float* wo = (const float*)d_in[7];
    const float* bo = (const float*)d_in[8];

    __half *xh, *wh, *q, *k, *v, *oh;
    cudaGetSymbolAddress((void**)&xh, g_xh);
    cudaGetSymbolAddress((void**)&wh, g_wh);
    cudaGetSymbolAddress((void**)&q,  g_q);
    cudaGetSymbolAddress((void**)&k,  g_k);
    cudaGetSymbolAddress((void**)&v,  g_v);
    cudaGetSymbolAddress((void**)&oh, g_oh);

    convert_all<<<4096, 256>>>(x, wq, wk, wv, wo, xh, wh);

    cudaFuncSetAttribute(qkv_gemm, cudaFuncAttributeMaxDynamicSharedMemorySize, QKV_SMEM);
    cudaFuncSetAttribute(out_gemm, cudaFuncAttributeMaxDynamicSharedMemorySize, GEMM256_SMEM);
    cudaFuncSetAttribute(attn_mma, cudaFuncAttributeMaxDynamicSharedMemorySize, ATT_SMEM);

    // Fused Q,K,V projection: 64x128 tiles, grid (64, 24), 3 CTA/SM
    qkv_gemm<<<dim3(MTOT / 64, 24), 128, QKV_SMEM>>>(
        xh, wh, bq, bk, bv, q, k, v);

    // Attention: BQ=64, grid (32, 32), 128 threads, 4 CTA/SM
    attn_mma<<<dim3(LL / 64, BB * HH), 128, ATT_SMEM>>>(q, k, v, oh);

    // Output projection: 128x256 tiles, grid (32, 4) = 128 CTAs, one wave
    out_gemm<<<dim3(MTOT / 128, 4), 256, GEMM256_SMEM>>>(
        oh, wh + 3*(size_t)DD*DD, bo, (float*)d_out);
}